// round 15
// baseline (speedup 1.0000x reference)
#include <cuda_runtime.h>
#include <cuda_bf16.h>
#include <cstdint>

// B=4096, T=256, I=6, H=64, gates=3H=192, 2 GRU layers + FC(H->1)
#define T_STEPS 256
#define I_DIM   6
#define HDIM    64
#define G3      192
#define BB      32
#define NT      256
#define NBPT    8
#define NCTA    128

#define WROW 144                 // bytes per row: 72 bf16 (64 used + pad)
#define WT   (G3 * WROW)         // 27648 B per weight tile
#define HT   (BB * WROW)         // 4608 B per h tile

// ---------------- SMEM layout (byte offsets) ----------------
#define SM_W0HI  0
#define SM_W0LO  (SM_W0HI + WT)
#define SM_W1IHI (SM_W0LO + WT)
#define SM_W1ILO (SM_W1IHI + WT)
#define SM_W1HHI (SM_W1ILO + WT)
#define SM_W1HLO (SM_W1HHI + WT)
#define SM_H1HI  (SM_W1HLO + WT)
#define SM_H1LO  (SM_H1HI + HT)
#define SM_H2HI  (SM_H1LO + HT)
#define SM_H2LO  (SM_H2HI + HT)
#define SM_WIH0  (SM_H2LO + HT)           // f32 [192][9]
#define SM_BIAS  (SM_WIH0 + G3 * 9 * 4)
#define SM_XS    (SM_BIAS + 4 * G3 * 4)   // [2][32][8] f32
#define SM_WFC   (SM_XS + 2 * BB * 8 * 4)
#define SM_BFC   (SM_WFC + HDIM * 4)
#define SM_EXA   (((SM_BFC + 4) + 127) & ~127)  // [128][33] f32
#define SM_EXN   (SM_EXA + 128 * 33 * 4)        // [64][33]
#define SM_EXX   (SM_EXN + 64 * 33 * 4)         // [64][33]
#define SM_TOTAL (SM_EXX + 64 * 33 * 4 + 128)
static_assert(SM_TOTAL < 227 * 1024, "smem over budget");

__device__ __forceinline__ uint32_t smem_u32(const void* p) {
    uint32_t a;
    asm("{ .reg .u64 t; cvta.to.shared.u64 t, %1; cvt.u32.u64 %0, t; }"
        : "=r"(a) : "l"(p));
    return a;
}
__device__ __forceinline__ void ldsm4(uint32_t addr, uint32_t r[4]) {
    asm volatile("ldmatrix.sync.aligned.m8n8.x4.shared.b16 {%0,%1,%2,%3}, [%4];"
                 : "=r"(r[0]), "=r"(r[1]), "=r"(r[2]), "=r"(r[3]) : "r"(addr));
}
__device__ __forceinline__ void mma16816(float d[4], const uint32_t a[4],
                                         const uint32_t b[2]) {
    asm volatile(
        "mma.sync.aligned.m16n8k16.row.col.f32.bf16.bf16.f32 "
        "{%0,%1,%2,%3}, {%4,%5,%6,%7}, {%8,%9}, {%0,%1,%2,%3};"
        : "+f"(d[0]), "+f"(d[1]), "+f"(d[2]), "+f"(d[3])
        : "r"(a[0]), "r"(a[1]), "r"(a[2]), "r"(a[3]), "r"(b[0]), "r"(b[1]));
}
__device__ __forceinline__ float sigf(float v) {
    return __fdividef(1.0f, 1.0f + __expf(-v));
}
__device__ __forceinline__ float tanhfast(float v) {
    float c = fminf(fmaxf(v, -15.0f), 15.0f);
    float e = __expf(2.0f * c);
    return __fdividef(e - 1.0f, e + 1.0f);
}
__device__ __forceinline__ void split_store(char* base, float h) {
    __nv_bfloat16 hi = __float2bfloat16(h);
    float hif = __bfloat162float(hi);
    __nv_bfloat16 lo = __float2bfloat16(h - hif);
    *(__nv_bfloat16*)(base) = hi;
    *(__nv_bfloat16*)(base + HT) = lo;
}

__global__ __launch_bounds__(NT) void gru_mma_kernel(
    const float* __restrict__ x,
    const float* __restrict__ W_ih0, const float* __restrict__ W_hh0,
    const float* __restrict__ b_ih0, const float* __restrict__ b_hh0,
    const float* __restrict__ W_ih1, const float* __restrict__ W_hh1,
    const float* __restrict__ b_ih1, const float* __restrict__ b_hh1,
    const float* __restrict__ W_fc,  const float* __restrict__ b_fc,
    float* __restrict__ out)
{
    extern __shared__ char smem[];
    const uint32_t sb = smem_u32(smem);
    const int tid = threadIdx.x;
    const int lane = tid & 31, wid = tid >> 5;
    const int b0 = blockIdx.x * BB;

    // ---- Stage weights: fp32 -> bf16 hi/lo row-major tiles ----
    for (int i = tid; i < G3 * HDIM; i += NT) {
        int r = i >> 6, c = i & 63;
        int off = r * WROW + c * 2;
        {
            float w = W_hh0[i];
            __nv_bfloat16 hi = __float2bfloat16(w);
            __nv_bfloat16 lo = __float2bfloat16(w - __bfloat162float(hi));
            *(__nv_bfloat16*)(smem + SM_W0HI + off) = hi;
            *(__nv_bfloat16*)(smem + SM_W0LO + off) = lo;
        }
        {
            float w = W_ih1[i];
            __nv_bfloat16 hi = __float2bfloat16(w);
            __nv_bfloat16 lo = __float2bfloat16(w - __bfloat162float(hi));
            *(__nv_bfloat16*)(smem + SM_W1IHI + off) = hi;
            *(__nv_bfloat16*)(smem + SM_W1ILO + off) = lo;
        }
        {
            float w = W_hh1[i];
            __nv_bfloat16 hi = __float2bfloat16(w);
            __nv_bfloat16 lo = __float2bfloat16(w - __bfloat162float(hi));
            *(__nv_bfloat16*)(smem + SM_W1HHI + off) = hi;
            *(__nv_bfloat16*)(smem + SM_W1HLO + off) = lo;
        }
    }
    float* wih0 = (float*)(smem + SM_WIH0);
    for (int i = tid; i < G3 * I_DIM; i += NT)
        wih0[(i / I_DIM) * 9 + (i % I_DIM)] = W_ih0[i];
    float* bias = (float*)(smem + SM_BIAS);
    for (int i = tid; i < G3; i += NT) {
        bias[i]          = b_ih0[i];
        bias[G3 + i]     = b_hh0[i];
        bias[2 * G3 + i] = b_ih1[i];
        bias[3 * G3 + i] = b_hh1[i];
    }
    // zero all 4 h tiles
    for (int i = tid; i < 4 * HT / 4; i += NT)
        ((uint32_t*)(smem + SM_H1HI))[i] = 0u;
    float* xsp = (float*)(smem + SM_XS);
    if (tid < HDIM) ((float*)(smem + SM_WFC))[tid] = W_fc[tid];
    if (tid == 0) *(float*)(smem + SM_BFC) = b_fc[0];

    const bool is_pref = (tid < BB * I_DIM);
    const int lb = is_pref ? (tid / I_DIM) : 0;
    const int li = is_pref ? (tid % I_DIM) : 0;
    const float* xlane = x + (size_t)(b0 + lb) * T_STEPS * I_DIM + li;
    if (is_pref) xsp[lb * 8 + li] = xlane[0];
    __syncthreads();

    // ---- MMA decomposition (identical mapping to R14, verified) ----
    const int nh = wid >> 2;
    const int mtbase = 3 * (wid & 3);
    const uint32_t aOff = (uint32_t)((lane & 15) * WROW + (((lane >> 4) << 3) << 1));
    const uint32_t bOff = (uint32_t)(((((lane >> 4) << 3) + (lane & 7)) * WROW) +
                                     (((lane >> 3) & 1) << 4));
    const uint32_t bNH = (uint32_t)(nh * 16 * WROW);
    const int rb = lane >> 2;
    const int cb = nh * 16 + 2 * (lane & 3);

    // ---- Activation mapping ----
    const int gg = tid & 63;
    const int bg = tid >> 6;
    const int bb0 = bg * NBPT;
    const float brC0 = bias[gg] + bias[G3 + gg];
    const float bzC0 = bias[gg + 64] + bias[G3 + gg + 64];
    const float bxn0 = bias[gg + 128];
    const float bhn0 = bias[G3 + gg + 128];
    const float br1  = bias[2 * G3 + gg] + bias[3 * G3 + gg];
    const float bz1  = bias[2 * G3 + gg + 64] + bias[3 * G3 + gg + 64];
    const float bxn1 = bias[2 * G3 + gg + 128];
    const float bhn1 = bias[3 * G3 + gg + 128];

    float h1reg[NBPT], h2reg[NBPT];
    #pragma unroll
    for (int b = 0; b < NBPT; ++b) { h1reg[b] = 0.0f; h2reg[b] = 0.0f; }

    float* exA = (float*)(smem + SM_EXA);
    float* exN = (float*)(smem + SM_EXN);
    float* exX = (float*)(smem + SM_EXX);

    // ======================================================================
    // Fused loop: iteration t computes L0(t) AND L1(t-1).
    // All three GEMMs share one MMA phase (inputs: H1(t-1), H2(t-2) tiles).
    // ======================================================================
    for (int t = 0; t < T_STEPS; ++t) {
        const int cur = t & 1, nxt = cur ^ 1;
        const float* xcur = xsp + cur * BB * 8;

        float a0[3][2][4], aX[3][2][4], aH[3][2][4];
        #pragma unroll
        for (int j = 0; j < 3; ++j)
            #pragma unroll
            for (int tt = 0; tt < 2; ++tt)
                #pragma unroll
                for (int e = 0; e < 4; ++e) {
                    a0[j][tt][e] = 0.0f; aX[j][tt][e] = 0.0f; aH[j][tt][e] = 0.0f;
                }
        // -------- Unified MMA phase: 3 independent streams --------
        #pragma unroll
        for (int kt = 0; kt < 4; ++kt) {
            uint32_t bh1[4], bl1[4], bh2[4], bl2[4];
            ldsm4(sb + SM_H1HI + bNH + kt * 32 + bOff, bh1);
            ldsm4(sb + SM_H1LO + bNH + kt * 32 + bOff, bl1);
            ldsm4(sb + SM_H2HI + bNH + kt * 32 + bOff, bh2);
            ldsm4(sb + SM_H2LO + bNH + kt * 32 + bOff, bl2);
            #pragma unroll
            for (int j = 0; j < 3; ++j) {
                uint32_t wa = (uint32_t)((mtbase + j) * 16 * WROW + kt * 32) + aOff;
                uint32_t ah[4], al[4];
                ldsm4(sb + SM_W0HI + wa, ah);
                ldsm4(sb + SM_W0LO + wa, al);
                mma16816(a0[j][0], ah, &bh1[0]);
                mma16816(a0[j][1], ah, &bh1[2]);
                mma16816(a0[j][0], ah, &bl1[0]);
                mma16816(a0[j][1], ah, &bl1[2]);
                mma16816(a0[j][0], al, &bh1[0]);
                mma16816(a0[j][1], al, &bh1[2]);
                ldsm4(sb + SM_W1IHI + wa, ah);
                ldsm4(sb + SM_W1ILO + wa, al);
                mma16816(aX[j][0], ah, &bh1[0]);
                mma16816(aX[j][1], ah, &bh1[2]);
                mma16816(aX[j][0], ah, &bl1[0]);
                mma16816(aX[j][1], ah, &bl1[2]);
                mma16816(aX[j][0], al, &bh1[0]);
                mma16816(aX[j][1], al, &bh1[2]);
                ldsm4(sb + SM_W1HHI + wa, ah);
                ldsm4(sb + SM_W1HLO + wa, al);
                mma16816(aH[j][0], ah, &bh2[0]);
                mma16816(aH[j][1], ah, &bh2[2]);
                mma16816(aH[j][0], ah, &bl2[0]);
                mma16816(aH[j][1], ah, &bl2[2]);
                mma16816(aH[j][0], al, &bh2[0]);
                mma16816(aH[j][1], al, &bh2[2]);
            }
        }
        // x-side GEMV (fp32, I=6)
        float xr[NBPT], xz[NBPT], xn[NBPT];
        #pragma unroll
        for (int b = 0; b < NBPT; ++b) { xr[b] = brC0; xz[b] = bzC0; xn[b] = bxn0; }
        #pragma unroll
        for (int k = 0; k < I_DIM; ++k) {
            float wr = wih0[gg * 9 + k], wz = wih0[(gg + 64) * 9 + k],
                  wn = wih0[(gg + 128) * 9 + k];
            #pragma unroll
            for (int b = 0; b < NBPT; ++b) {
                float xv = xcur[(bb0 + b) * 8 + k];
                xr[b] = fmaf(xv, wr, xr[b]);
                xz[b] = fmaf(xv, wz, xz[b]);
                xn[b] = fmaf(xv, wn, xn[b]);
            }
        }
        float xpref = 0.0f;
        const bool do_pref = is_pref && (t + 1 < T_STEPS);
        if (do_pref) xpref = xlane[(size_t)(t + 1) * I_DIM];

        // -------- store L0 exchange --------
        #pragma unroll
        for (int j = 0; j < 3; ++j) {
            int mt = mtbase + j;
            float* dst = (mt < 8) ? exA : exN;
            int r0 = ((mt < 8) ? mt : mt - 8) * 16 + rb;
            #pragma unroll
            for (int tt = 0; tt < 2; ++tt) {
                int c = cb + tt * 8;
                dst[r0 * 33 + c]           = a0[j][tt][0];
                dst[r0 * 33 + c + 1]       = a0[j][tt][1];
                dst[(r0 + 8) * 33 + c]     = a0[j][tt][2];
                dst[(r0 + 8) * 33 + c + 1] = a0[j][tt][3];
            }
        }
        __syncthreads();

        // -------- L0(t) activations -> h1 tile --------
        #pragma unroll
        for (int b = 0; b < NBPT; ++b) {
            int bb = bb0 + b;
            float r = sigf(xr[b] + exA[gg * 33 + bb]);
            float z = sigf(xz[b] + exA[(gg + 64) * 33 + bb]);
            float n = tanhfast(fmaf(r, exN[gg * 33 + bb] + bhn0, xn[b]));
            float h = fmaf(z, h1reg[b] - n, n);
            h1reg[b] = h;
            split_store(smem + SM_H1HI + bb * WROW + gg * 2, h);
        }
        if (do_pref) xsp[nxt * BB * 8 + lb * 8 + li] = xpref;
        __syncthreads();

        // -------- store L1 exchange (reuses buffers) --------
        #pragma unroll
        for (int j = 0; j < 3; ++j) {
            int mt = mtbase + j;
            if (mt < 8) {
                int r0 = mt * 16 + rb;
                #pragma unroll
                for (int tt = 0; tt < 2; ++tt) {
                    int c = cb + tt * 8;
                    exA[r0 * 33 + c]           = aX[j][tt][0] + aH[j][tt][0];
                    exA[r0 * 33 + c + 1]       = aX[j][tt][1] + aH[j][tt][1];
                    exA[(r0 + 8) * 33 + c]     = aX[j][tt][2] + aH[j][tt][2];
                    exA[(r0 + 8) * 33 + c + 1] = aX[j][tt][3] + aH[j][tt][3];
                }
            } else {
                int r0 = (mt - 8) * 16 + rb;
                #pragma unroll
                for (int tt = 0; tt < 2; ++tt) {
                    int c = cb + tt * 8;
                    exN[r0 * 33 + c]           = aH[j][tt][0];
                    exN[r0 * 33 + c + 1]       = aH[j][tt][1];
                    exN[(r0 + 8) * 33 + c]     = aH[j][tt][2];
                    exN[(r0 + 8) * 33 + c + 1] = aH[j][tt][3];
                    exX[r0 * 33 + c]           = aX[j][tt][0];
                    exX[r0 * 33 + c + 1]       = aX[j][tt][1];
                    exX[(r0 + 8) * 33 + c]     = aX[j][tt][2];
                    exX[(r0 + 8) * 33 + c + 1] = aX[j][tt][3];
                }
            }
        }
        __syncthreads();

        // -------- L1(t-1) activations -> h2 tile (skip at t=0) --------
        if (t > 0) {
            #pragma unroll
            for (int b = 0; b < NBPT; ++b) {
                int bb = bb0 + b;
                float r = sigf(exA[gg * 33 + bb] + br1);
                float z = sigf(exA[(gg + 64) * 33 + bb] + bz1);
                float n = tanhfast(fmaf(r, exN[gg * 33 + bb] + bhn1,
                                        exX[gg * 33 + bb] + bxn1));
                float h = fmaf(z, h2reg[b] - n, n);
                h2reg[b] = h;
                split_store(smem + SM_H2HI + bb * WROW + gg * 2, h);
            }
        }
        __syncthreads();
    }

    // ======== Peel: L1(255) — inputs H1(255), H2(254) ========
    {
        float aX[3][2][4], aH[3][2][4];
        #pragma unroll
        for (int j = 0; j < 3; ++j)
            #pragma unroll
            for (int tt = 0; tt < 2; ++tt)
                #pragma unroll
                for (int e = 0; e < 4; ++e) { aX[j][tt][e] = 0.0f; aH[j][tt][e] = 0.0f; }
        #pragma unroll
        for (int kt = 0; kt < 4; ++kt) {
            uint32_t ph[4], pl[4], qh[4], ql[4];
            ldsm4(sb + SM_H1HI + bNH + kt * 32 + bOff, ph);
            ldsm4(sb + SM_H1LO + bNH + kt * 32 + bOff, pl);
            ldsm4(sb + SM_H2HI + bNH + kt * 32 + bOff, qh);
            ldsm4(sb + SM_H2LO + bNH + kt * 32 + bOff, ql);
            #pragma unroll
            for (int j = 0; j < 3; ++j) {
                uint32_t wa = (uint32_t)((mtbase + j) * 16 * WROW + kt * 32) + aOff;
                uint32_t ah[4], al[4];
                ldsm4(sb + SM_W1IHI + wa, ah);
                ldsm4(sb + SM_W1ILO + wa, al);
                mma16816(aX[j][0], ah, &ph[0]);
                mma16816(aX[j][1], ah, &ph[2]);
                mma16816(aX[j][0], ah, &pl[0]);
                mma16816(aX[j][1], ah, &pl[2]);
                mma16816(aX[j][0], al, &ph[0]);
                mma16816(aX[j][1], al, &ph[2]);
                ldsm4(sb + SM_W1HHI + wa, ah);
                ldsm4(sb + SM_W1HLO + wa, al);
                mma16816(aH[j][0], ah, &qh[0]);
                mma16816(aH[j][1], ah, &qh[2]);
                mma16816(aH[j][0], ah, &ql[0]);
                mma16816(aH[j][1], ah, &ql[2]);
                mma16816(aH[j][0], al, &qh[0]);
                mma16816(aH[j][1], al, &qh[2]);
            }
        }
        #pragma unroll
        for (int j = 0; j < 3; ++j) {
            int mt = mtbase + j;
            if (mt < 8) {
                int r0 = mt * 16 + rb;
                #pragma unroll
                for (int tt = 0; tt < 2; ++tt) {
                    int c = cb + tt * 8;
                    exA[r0 * 33 + c]           = aX[j][tt][0] + aH[j][tt][0];
                    exA[r0 * 33 + c + 1]       = aX[j][tt][1] + aH[j][tt][1];
                    exA[(r0 + 8) * 33 + c]     = aX[j][tt][2] + aH[j][tt][2];
                    exA[(r0 + 8) * 33 + c + 1] = aX[j][tt][3] + aH[j][tt][3];
                }
            } else {
                int r0 = (mt - 8) * 16 + rb;
                #pragma unroll
                for (int tt = 0; tt < 2; ++tt) {
                    int c = cb + tt * 8;
                    exN[r0 * 33 + c]           = aH[j][tt][0];
                    exN[r0 * 33 + c + 1]       = aH[j][tt][1];
                    exN[(r0 + 8) * 33 + c]     = aH[j][tt][2];
                    exN[(r0 + 8) * 33 + c + 1] = aH[j][tt][3];
                    exX[r0 * 33 + c]           = aX[j][tt][0];
                    exX[r0 * 33 + c + 1]       = aX[j][tt][1];
                    exX[(r0 + 8) * 33 + c]     = aX[j][tt][2];
                    exX[(r0 + 8) * 33 + c + 1] = aX[j][tt][3];
                }
            }
        }
        __syncthreads();
        #pragma unroll
        for (int b = 0; b < NBPT; ++b) {
            int bb = bb0 + b;
            float r = sigf(exA[gg * 33 + bb] + br1);
            float z = sigf(exA[(gg + 64) * 33 + bb] + bz1);
            float n = tanhfast(fmaf(r, exN[gg * 33 + bb] + bhn1,
                                    exX[gg * 33 + bb] + bxn1));
            h2reg[b] = fmaf(z, h2reg[b] - n, n);
        }
        __syncthreads();
    }

    // ---- Final FC: out[b] = h2 . wfc + bfc ----
    #pragma unroll
    for (int b = 0; b < NBPT; ++b) exA[(bb0 + b) * 68 + gg] = h2reg[b];
    __syncthreads();
    if (tid < BB) {
        const float* wfc = (const float*)(smem + SM_WFC);
        float acc2 = *(const float*)(smem + SM_BFC);
        #pragma unroll 8
        for (int k = 0; k < HDIM; ++k)
            acc2 = fmaf(exA[tid * 68 + k], wfc[k], acc2);
        out[b0 + tid] = acc2;
    }
}

extern "C" void kernel_launch(void* const* d_in, const int* in_sizes, int n_in,
                              void* d_out, int out_size)
{
    const float* x     = (const float*)d_in[0];
    const float* W_ih0 = (const float*)d_in[1];
    const float* W_hh0 = (const float*)d_in[2];
    const float* b_ih0 = (const float*)d_in[3];
    const float* b_hh0 = (const float*)d_in[4];
    const float* W_ih1 = (const float*)d_in[5];
    const float* W_hh1 = (const float*)d_in[6];
    const float* b_ih1 = (const float*)d_in[7];
    const float* b_hh1 = (const float*)d_in[8];
    const float* W_fc  = (const float*)d_in[9];
    const float* b_fc  = (const float*)d_in[10];
    float* out = (float*)d_out;
    (void)in_sizes; (void)n_in; (void)out_size;

    cudaFuncSetAttribute(gru_mma_kernel,
                         cudaFuncAttributeMaxDynamicSharedMemorySize, SM_TOTAL);
    gru_mma_kernel<<<NCTA, NT, SM_TOTAL>>>(
        x, W_ih0, W_hh0, b_ih0, b_hh0,
        W_ih1, W_hh1, b_ih1, b_hh1,
        W_fc, b_fc, out);
}